// round 16
// baseline (speedup 1.0000x reference)
#include <cuda_runtime.h>
#include <cuda_fp16.h>
#include <stdint.h>

constexpr int B  = 2;
constexpr int SQ = 2048;
constexpr int SK = 2048;
constexpr int D  = 1024;
constexpr int NH = 16;
constexpr int H  = 64;
constexpr int M  = B * SQ;
constexpr float EPS = 1e-5f;

// ---------------- device scratch ----------------
__device__ __align__(16) __half g_xq_hi [M * D];
__device__ __align__(16) __half g_xq_lo [M * D];
__device__ __align__(16) __half g_xkv_hi[M * D];
__device__ __align__(16) __half g_xkv_lo[M * D];
__device__ __align__(16) __half g_Wq_hi [D * D];
__device__ __align__(16) __half g_Wq_lo [D * D];
__device__ __align__(16) __half g_Wk_hi [D * D];
__device__ __align__(16) __half g_Wk_lo [D * D];
__device__ __align__(16) __half g_Wv_hi [D * D];
__device__ __align__(16) __half g_Wv_lo [D * D];
__device__ __align__(16) __half g_Wo_hi [D * D];
__device__ __align__(16) __half g_Wo_lo [D * D];
__device__ __align__(16) float  g_qf [M * D];
__device__ __align__(16) float  g_kf [M * D];
__device__ __align__(16) __half g_qh_hi[M * D];
__device__ __align__(16) __half g_qh_lo[M * D];
__device__ __align__(16) __half g_kh_hi[M * D];
__device__ __align__(16) __half g_kh_lo[M * D];
__device__ __align__(16) __half g_vh_hi[M * D];
__device__ __align__(16) __half g_zh_hi[M * D];

__device__ __forceinline__ void split2(float x, __half& hi, __half& lo) {
    __half h = __float2half(x);
    hi = h;
    lo = __float2half(x - __half2float(h));
}

__device__ __forceinline__ void cp16(void* dst, const void* src) {
    uint32_t d = (uint32_t)__cvta_generic_to_shared(dst);
    asm volatile("cp.async.cg.shared.global [%0], [%1], 16;\n" :: "r"(d), "l"(src));
}
__device__ __forceinline__ void cp_commit() { asm volatile("cp.async.commit_group;\n"); }
template <int N>
__device__ __forceinline__ void cp_wait() { asm volatile("cp.async.wait_group %0;\n" :: "n"(N)); }

// ---- mma.sync / ldmatrix primitives ----
__device__ __forceinline__ uint32_t smem_u32(const void* p) {
    return (uint32_t)__cvta_generic_to_shared(p);
}
__device__ __forceinline__ void ldsm_x4(uint32_t (&r)[4], uint32_t a) {
    asm volatile("ldmatrix.sync.aligned.m8n8.x4.shared.b16 {%0,%1,%2,%3}, [%4];"
                 : "=r"(r[0]), "=r"(r[1]), "=r"(r[2]), "=r"(r[3]) : "r"(a));
}
__device__ __forceinline__ void ldsm_x4t(uint32_t (&r)[4], uint32_t a) {
    asm volatile("ldmatrix.sync.aligned.m8n8.x4.trans.shared.b16 {%0,%1,%2,%3}, [%4];"
                 : "=r"(r[0]), "=r"(r[1]), "=r"(r[2]), "=r"(r[3]) : "r"(a));
}
__device__ __forceinline__ void mma16816s(float (&d)[4], const uint32_t (&a)[4],
                                          uint32_t b0, uint32_t b1) {
    asm volatile("mma.sync.aligned.m16n8k16.row.col.f32.f16.f16.f32 "
                 "{%0,%1,%2,%3}, {%4,%5,%6,%7}, {%8,%9}, {%0,%1,%2,%3};"
                 : "+f"(d[0]), "+f"(d[1]), "+f"(d[2]), "+f"(d[3])
                 : "r"(a[0]), "r"(a[1]), "r"(a[2]), "r"(a[3]), "r"(b0), "r"(b1));
}
__device__ __forceinline__ void split_pack(float f0, float f1, uint32_t& hi, uint32_t& lo) {
    __half h0 = __float2half_rn(f0), h1 = __float2half_rn(f1);
    __half2 hh = __halves2half2(h0, h1);
    hi = *reinterpret_cast<uint32_t*>(&hh);
    __half2 ll = __halves2half2(__float2half_rn(f0 - __half2float(h0)),
                                __float2half_rn(f1 - __half2float(h1)));
    lo = *reinterpret_cast<uint32_t*>(&ll);
}

// ---------------- conversion kernels ----------------
__global__ void k_convert_x(const float* __restrict__ xq, const float* __restrict__ xkv) {
    int i = blockIdx.x * blockDim.x + threadIdx.x;
    if (i < M * D) {
        split2(xq [i], g_xq_hi [i], g_xq_lo [i]);
        split2(xkv[i], g_xkv_hi[i], g_xkv_lo[i]);
    }
}

__global__ void k_convert_w(const float* __restrict__ WQ, const float* __restrict__ WK,
                            const float* __restrict__ WV, const float* __restrict__ WO) {
    int i = blockIdx.x * blockDim.x + threadIdx.x;
    if (i < D * D) {
        int d   = i >> 10;
        int col = i & 1023;
        int n   = col >> 6;
        int h   = col & 63;
        int src = n * D * H + d * H + h;   // W[n][d][h] -> [D, N*H]
        split2(WQ[src], g_Wq_hi[i], g_Wq_lo[i]);
        split2(WK[src], g_Wk_hi[i], g_Wk_lo[i]);
        split2(WV[src], g_Wv_hi[i], g_Wv_lo[i]);
        split2(WO[i],   g_Wo_hi[i], g_Wo_lo[i]);  // [N,H,D] flat == [N*H,D]
    }
}

// ---------------- GEMM: 128x128x32, 2-stage, raw mma.sync, register epilogue ----
constexpr int BM = 128, BN = 128, BK = 32;
constexpr int A_LD = 40;    // halfs (32 + 8 pad); row stride 80 B (16B-aligned)
constexpr int B_LD = 136;   // halfs (128 + 8 pad); row stride 272 B (16B-aligned)
constexpr int A_BYTES = BM * A_LD * 2;
constexpr int B_BYTES = BK * B_LD * 2;
constexpr int STAGE_BYTES = 2 * A_BYTES + 2 * B_BYTES;  // 37888
constexpr int GEMM_SMEM = 2 * STAGE_BYTES;              // 75776 -> 2 CTAs/SM

// ALO: include the A_lo * B_hi correction term (3-term split) or not (2-term).
// Leaves result in acc[mi][nt][4]; C layout: row = wm*64+mi*16+(lane>>2)(+8),
// col = wn*32 + nt*8 + 2*(lane&3).
template <bool ALO>
__device__ __forceinline__ void gemm_core_mma(const __half* A_hi, const __half* A_lo,
                                              const __half* B_hi, const __half* B_lo,
                                              char* smem, int row0, int col0, int tid,
                                              float (&acc)[4][4][4]) {
    const int warp   = tid >> 5;
    const int lane   = tid & 31;
    const int warp_m = warp >> 2;       // 0..1 -> 64 rows
    const int warp_n = warp & 3;        // 0..3 -> 32 cols

    auto load_stage = [&](int s, int k0) {
        char* st = smem + s * STAGE_BYTES;
        __half* sAh = (__half*)st;
        __half* sAl = (__half*)(st + A_BYTES);
        __half* sBh = (__half*)(st + 2 * A_BYTES);
        __half* sBl = (__half*)(st + 2 * A_BYTES + B_BYTES);
#pragma unroll
        for (int t = 0; t < 2; t++) {
            int idx = tid + t * 256;
            int ar = idx >> 2, ac = (idx & 3) * 8;
            size_t ai = (size_t)(row0 + ar) * D + k0 + ac;
            cp16(&sAh[ar * A_LD + ac], &A_hi[ai]);
            if (ALO) cp16(&sAl[ar * A_LD + ac], &A_lo[ai]);
            int br = idx >> 4, bc = (idx & 15) * 8;
            size_t bi = (size_t)(k0 + br) * D + col0 + bc;
            cp16(&sBh[br * B_LD + bc], &B_hi[bi]);
            cp16(&sBl[br * B_LD + bc], &B_lo[bi]);
        }
        cp_commit();
    };

#pragma unroll
    for (int i = 0; i < 4; i++)
#pragma unroll
        for (int j = 0; j < 4; j++)
#pragma unroll
            for (int e = 0; e < 4; e++) acc[i][j][e] = 0.0f;

    // ldmatrix lane addressing (same mapping as the attention kernel)
    const int a_row = lane & 15;
    const int a_col = (lane >> 4) * 8;
    const int b_row = (lane & 8) + (lane & 7);     // x4t: rows +0/+8
    const int b_col = ((lane & 16) >> 1);          // cols +0/+8

    constexpr int NIT = D / BK;
    load_stage(0, 0);

    for (int it = 0; it < NIT; it++) {
        if (it + 1 < NIT) {
            load_stage((it + 1) & 1, (it + 1) * BK);
            cp_wait<1>();
        } else {
            cp_wait<0>();
        }
        __syncthreads();

        char* st = smem + (it & 1) * STAGE_BYTES;
        __half* sAh = (__half*)st;
        __half* sAl = (__half*)(st + A_BYTES);
        __half* sBh = (__half*)(st + 2 * A_BYTES);
        __half* sBl = (__half*)(st + 2 * A_BYTES + B_BYTES);

#pragma unroll
        for (int kf = 0; kf < 2; kf++) {
            uint32_t ahi[4][4], alo[4][4];
#pragma unroll
            for (int mi = 0; mi < 4; mi++) {
                int r = warp_m * 64 + mi * 16 + a_row;
                ldsm_x4(ahi[mi], smem_u32(&sAh[r * A_LD + kf * 16 + a_col]));
                if (ALO) ldsm_x4(alo[mi], smem_u32(&sAl[r * A_LD + kf * 16 + a_col]));
            }
#pragma unroll
            for (int ni = 0; ni < 2; ni++) {   // two 16-col groups -> 4 n8 tiles
                int c = warp_n * 32 + ni * 16 + b_col;
                uint32_t bh[4], bl[4];
                ldsm_x4t(bh, smem_u32(&sBh[(kf * 16 + b_row) * B_LD + c]));
                ldsm_x4t(bl, smem_u32(&sBl[(kf * 16 + b_row) * B_LD + c]));
#pragma unroll
                for (int mi = 0; mi < 4; mi++) {
                    mma16816s(acc[mi][2 * ni],     ahi[mi], bh[0], bh[1]);
                    if (ALO) mma16816s(acc[mi][2 * ni], alo[mi], bh[0], bh[1]);
                    mma16816s(acc[mi][2 * ni],     ahi[mi], bl[0], bl[1]);
                    mma16816s(acc[mi][2 * ni + 1], ahi[mi], bh[2], bh[3]);
                    if (ALO) mma16816s(acc[mi][2 * ni + 1], alo[mi], bh[2], bh[3]);
                    mma16816s(acc[mi][2 * ni + 1], ahi[mi], bl[2], bl[3]);
                }
            }
        }
        __syncthreads();
    }
}

// ---------------- fused QKV GEMM (Q/K 3-term; V 2-term), register epilogue ------
__global__ __launch_bounds__(256) void k_qkv(const float* __restrict__ b_Q,
                                             const float* __restrict__ b_K,
                                             const float* __restrict__ b_V,
                                             float* __restrict__ v_out) {
    extern __shared__ __align__(16) char smem[];
    const int tid  = threadIdx.x;
    const int lane = tid & 31;
    const int warp = tid >> 5;
    const int z    = blockIdx.z;
    const int row0 = blockIdx.y * BM;
    const int col0 = blockIdx.x * BN;

    float acc[4][4][4];
    if (z == 0)
        gemm_core_mma<true>(g_xq_hi, g_xq_lo, g_Wq_hi, g_Wq_lo, smem, row0, col0, tid, acc);
    else if (z == 1)
        gemm_core_mma<true>(g_xkv_hi, g_xkv_lo, g_Wk_hi, g_Wk_lo, smem, row0, col0, tid, acc);
    else
        gemm_core_mma<false>(g_xkv_hi, g_xkv_hi, g_Wv_hi, g_Wv_lo, smem, row0, col0, tid, acc);

    const float* bias = (z == 0) ? b_Q : (z == 1) ? b_K : b_V;
    const int rbase = row0 + (warp >> 2) * 64 + (lane >> 2);
    const int cbase = col0 + (warp & 3) * 32 + 2 * (lane & 3);

#pragma unroll
    for (int mi = 0; mi < 4; mi++) {
#pragma unroll
        for (int nt = 0; nt < 4; nt++) {
            int r = rbase + mi * 16;
            int c = cbase + nt * 8;
            float2 bb = *(const float2*)&bias[c];
            float v0 = acc[mi][nt][0] + bb.x, v1 = acc[mi][nt][1] + bb.y;
            float v2 = acc[mi][nt][2] + bb.x, v3 = acc[mi][nt][3] + bb.y;
            size_t gi0 = (size_t)r * D + c;
            size_t gi1 = (size_t)(r + 8) * D + c;
            if (z == 0) {
                *(float2*)&g_qf[gi0] = make_float2(v0, v1);
                *(float2*)&g_qf[gi1] = make_float2(v2, v3);
            } else if (z == 1) {
                *(float2*)&g_kf[gi0] = make_float2(v0, v1);
                *(float2*)&g_kf[gi1] = make_float2(v2, v3);
            } else {
                __half2 h0 = __floats2half2_rn(v0, v1);
                __half2 h1 = __floats2half2_rn(v2, v3);
                *(uint32_t*)&g_vh_hi[gi0] = *(uint32_t*)&h0;
                *(uint32_t*)&g_vh_hi[gi1] = *(uint32_t*)&h1;
                if (v_out) {
                    *(float2*)&v_out[gi0] = make_float2(v0, v1);
                    *(float2*)&v_out[gi1] = make_float2(v2, v3);
                }
            }
        }
    }
}

// ---------------- per-head LayerNorm over H=64 ----------------
template <int SEL>
__global__ void k_ln(const float* __restrict__ g, const float* __restrict__ bb,
                     float* __restrict__ out_f) {
    const float* in     = (SEL == 0) ? g_qf    : g_kf;
    __half*      out_hi = (SEL == 0) ? g_qh_hi : g_kh_hi;
    __half*      out_lo = (SEL == 0) ? g_qh_lo : g_kh_lo;

    int row  = blockIdx.x * 8 + (threadIdx.x >> 5);
    int lane = threadIdx.x & 31;
    const float* p = in + (size_t)row * H;
    float v0 = p[lane], v1 = p[lane + 32];
    float s = v0 + v1;
#pragma unroll
    for (int o = 16; o; o >>= 1) s += __shfl_xor_sync(0xffffffffu, s, o);
    float mean = s * (1.0f / 64.0f);
    float d0 = v0 - mean, d1 = v1 - mean;
    float q = d0 * d0 + d1 * d1;
#pragma unroll
    for (int o = 16; o; o >>= 1) q += __shfl_xor_sync(0xffffffffu, q, o);
    float rstd = rsqrtf(q * (1.0f / 64.0f) + EPS);
    float o0 = d0 * rstd * g[lane]      + bb[lane];
    float o1 = d1 * rstd * g[lane + 32] + bb[lane + 32];
    size_t base = (size_t)row * H;
    split2(o0, out_hi[base + lane],      out_lo[base + lane]);
    split2(o1, out_hi[base + lane + 32], out_lo[base + lane + 32]);
    if (out_f) {
        out_f[base + lane]      = o0;
        out_f[base + lane + 32] = o1;
    }
}

// ---------------- O GEMM (2-term), register epilogue ----------------
__global__ __launch_bounds__(256) void k_gemm_o(const float* __restrict__ bias,
                                                float* __restrict__ Cext) {
    extern __shared__ __align__(16) char smem[];
    const int tid  = threadIdx.x;
    const int lane = tid & 31;
    const int warp = tid >> 5;
    const int row0 = blockIdx.y * BM;
    const int col0 = blockIdx.x * BN;

    float acc[4][4][4];
    gemm_core_mma<false>(g_zh_hi, g_zh_hi, g_Wo_hi, g_Wo_lo, smem, row0, col0, tid, acc);

    const int rbase = row0 + (warp >> 2) * 64 + (lane >> 2);
    const int cbase = col0 + (warp & 3) * 32 + 2 * (lane & 3);
#pragma unroll
    for (int mi = 0; mi < 4; mi++) {
#pragma unroll
        for (int nt = 0; nt < 4; nt++) {
            int r = rbase + mi * 16;
            int c = cbase + nt * 8;
            float2 bb = *(const float2*)&bias[c];
            *(float2*)&Cext[(size_t)r * D + c] =
                make_float2(acc[mi][nt][0] + bb.x, acc[mi][nt][1] + bb.y);
            *(float2*)&Cext[(size_t)(r + 8) * D + c] =
                make_float2(acc[mi][nt][2] + bb.x, acc[mi][nt][3] + bb.y);
        }
    }
}

// ---------------- flash attention: register S/P/Z, reversed qt order ----------
constexpr int ATT_QHI = 0;                       // 18432
constexpr int ATT_QLO = 18432;                   // 18432
constexpr int ATT_KV0 = 36864;
constexpr int KV_STAGE_B = 27648;                // Khi, Klo, Vhi
constexpr int ATT_SMEM = ATT_KV0 + 2 * KV_STAGE_B;   // 92160 -> 2 CTAs/SM

__global__ __launch_bounds__(256, 2) void k_attn() {
    extern __shared__ __align__(16) char sm[];
    __half* Qhi = (__half*)(sm + ATT_QHI);
    __half* Qlo = (__half*)(sm + ATT_QLO);

    const int qt = (gridDim.x - 1) - blockIdx.x;   // heavy diagonal tiles first
    const int n = blockIdx.y, b = blockIdx.z;
    const int tid = threadIdx.x, warp = tid >> 5, lane = tid & 31;
    const int qbase = qt * 128;
    const int qr0 = qbase + warp * 16;

    auto load_kv = [&](int j, int s) {
        char* st = sm + ATT_KV0 + s * KV_STAGE_B;
        __half* Kh = (__half*)st;
        __half* Kl = (__half*)(st + 9216);
        __half* Vh = (__half*)(st + 18432);
        const int kbase = j * 64;
#pragma unroll
        for (int t = 0; t < 2; t++) {
            int idx = tid + t * 256;
            int r = idx >> 3, c8 = (idx & 7) * 8;
            size_t gi = (((size_t)b * SK + kbase + r) * NH + n) * H + c8;
            cp16(&Kh[r * 72 + c8], &g_kh_hi[gi]);
            cp16(&Kl[r * 72 + c8], &g_kh_lo[gi]);
            cp16(&Vh[r * 72 + c8], &g_vh_hi[gi]);
        }
        cp_commit();
    };

    // Q tile load
#pragma unroll
    for (int t = 0; t < 4; t++) {
        int idx = tid + t * 256;
        int r = idx >> 3, c8 = (idx & 7) * 8;
        size_t gi = (((size_t)b * SQ + qbase + r) * NH + n) * H + c8;
        *(uint4*)&Qhi[r * 72 + c8] = *(const uint4*)&g_qh_hi[gi];
        *(uint4*)&Qlo[r * 72 + c8] = *(const uint4*)&g_qh_lo[gi];
    }
    load_kv(0, 0);

    float z[8][4];
#pragma unroll
    for (int ht = 0; ht < 8; ht++)
#pragma unroll
        for (int e = 0; e < 4; e++) z[ht][e] = 0.0f;
    float m0 = -1e30f, m1 = -1e30f, l0 = 0.0f, l1 = 0.0f;

    const int qrow0 = qr0 + (lane >> 2);
    const int qrow1 = qrow0 + 8;

    const int a_row  = lane & 15;
    const int a_col  = (lane >> 4) * 8;
    const int kx_row = ((lane & 16) >> 1) + (lane & 7);
    const int kx_col = (lane & 8);
    const int vx_row = (lane & 8) + (lane & 7);
    const int vx_col = ((lane & 16) >> 1);

    const int jmax = 2 * qt + 1;
    __syncthreads();

    for (int j = 0; j <= jmax; j++) {
        const int kbase = j * 64;
        const int s = j & 1;
        __syncthreads();                       // compute(j-1) done; buffer s^1 free
        if (j < jmax) { load_kv(j + 1, s ^ 1); cp_wait<1>(); }
        else          { cp_wait<0>(); }
        __syncthreads();                       // stage s visible

        const bool active = (kbase <= qr0 + 15);
        if (active) {
            char* st = sm + ATT_KV0 + s * KV_STAGE_B;
            __half* Kh = (__half*)st;
            __half* Kl = (__half*)(st + 9216);
            __half* Vh = (__half*)(st + 18432);
            const bool needmask = (kbase + 63 > qr0);

            // ---- S = Q @ K^T (3-term split) ----
            float sreg[8][4];
#pragma unroll
            for (int nt = 0; nt < 8; nt++)
#pragma unroll
                for (int e = 0; e < 4; e++) sreg[nt][e] = 0.0f;

#pragma unroll
            for (int kk = 0; kk < 4; kk++) {
                uint32_t qh[4], ql[4];
                ldsm_x4(qh, smem_u32(&Qhi[(warp * 16 + a_row) * 72 + kk * 16 + a_col]));
                ldsm_x4(ql, smem_u32(&Qlo[(warp * 16 + a_row) * 72 + kk * 16 + a_col]));
#pragma unroll
                for (int nt2 = 0; nt2 < 4; nt2++) {
                    uint32_t kh[4], kl[4];
                    ldsm_x4(kh, smem_u32(&Kh[(nt2 * 16 + kx_row) * 72 + kk * 16 + kx_col]));
                    ldsm_x4(kl, smem_u32(&Kl[(nt2 * 16 + kx_row) * 72 + kk * 16 + kx_col]));
                    mma16816s(sreg[2 * nt2],     qh, kh[0], kh[1]);
                    mma16816s(sreg[2 * nt2],     ql, kh[0], kh[1]);
                    mma16816s(sreg[2 * nt2],     qh, kl[0], kl[1]);
                    mma16816s(sreg[2 * nt2 + 1], qh, kh[2], kh[3]);
                    mma16816s(sreg[2 * nt2 + 1], ql, kh[2], kh[3]);
                    mma16816s(sreg[2 * nt2 + 1], qh, kl[2], kl[3]);
                }
            }

            // ---- online softmax in registers ----
            float mx0 = -1e30f, mx1 = -1e30f;
#pragma unroll
            for (int nt = 0; nt < 8; nt++) {
                int colg = kbase + nt * 8 + 2 * (lane & 3);
                if (needmask) {
                    if (colg     > qrow0) sreg[nt][0] = -1e30f;
                    if (colg + 1 > qrow0) sreg[nt][1] = -1e30f;
                    if (colg     > qrow1) sreg[nt][2] = -1e30f;
                    if (colg + 1 > qrow1) sreg[nt][3] = -1e30f;
                }
                mx0 = fmaxf(mx0, fmaxf(sreg[nt][0], sreg[nt][1]));
                mx1 = fmaxf(mx1, fmaxf(sreg[nt][2], sreg[nt][3]));
            }
            mx0 = fmaxf(mx0, __shfl_xor_sync(0xffffffffu, mx0, 1));
            mx0 = fmaxf(mx0, __shfl_xor_sync(0xffffffffu, mx0, 2));
            mx1 = fmaxf(mx1, __shfl_xor_sync(0xffffffffu, mx1, 1));
            mx1 = fmaxf(mx1, __shfl_xor_sync(0xffffffffu, mx1, 2));

            float mn0 = fmaxf(m0, mx0), mn1 = fmaxf(m1, mx1);
            float al0 = __expf(m0 - mn0), al1 = __expf(m1 - mn1);
            float sum0 = 0.0f, sum1 = 0.0f;
#pragma unroll
            for (int nt = 0; nt < 8; nt++) {
                float p0 = (sreg[nt][0] > -1e29f) ? __expf(sreg[nt][0] - mn0) : 0.0f;
                float p1 = (sreg[nt][1] > -1e29f) ? __expf(sreg[nt][1] - mn0) : 0.0f;
                float p2 = (sreg[nt][2] > -1e29f) ? __expf(sreg[nt][2] - mn1) : 0.0f;
                float p3 = (sreg[nt][3] > -1e29f) ? __expf(sreg[nt][3] - mn1) : 0.0f;
                sreg[nt][0] = p0; sreg[nt][1] = p1; sreg[nt][2] = p2; sreg[nt][3] = p3;
                sum0 += p0 + p1;
                sum1 += p2 + p3;
            }
            sum0 += __shfl_xor_sync(0xffffffffu, sum0, 1);
            sum0 += __shfl_xor_sync(0xffffffffu, sum0, 2);
            sum1 += __shfl_xor_sync(0xffffffffu, sum1, 1);
            sum1 += __shfl_xor_sync(0xffffffffu, sum1, 2);
            m0 = mn0; m1 = mn1;
            l0 = l0 * al0 + sum0;
            l1 = l1 * al1 + sum1;
#pragma unroll
            for (int ht = 0; ht < 8; ht++) {
                z[ht][0] *= al0; z[ht][1] *= al0;
                z[ht][2] *= al1; z[ht][3] *= al1;
            }

            // ---- Z += P @ V (P hi+lo, V hi only) ----
#pragma unroll
            for (int kk2 = 0; kk2 < 4; kk2++) {
                uint32_t ahi[4], alo[4];
                split_pack(sreg[2 * kk2][0],     sreg[2 * kk2][1],     ahi[0], alo[0]);
                split_pack(sreg[2 * kk2][2],     sreg[2 * kk2][3],     ahi[1], alo[1]);
                split_pack(sreg[2 * kk2 + 1][0], sreg[2 * kk2 + 1][1], ahi[2], alo[2]);
                split_pack(sreg[2 * kk2 + 1][2], sreg[2 * kk2 + 1][3], ahi[3], alo[3]);
#pragma unroll
                for (int ht2 = 0; ht2 < 4; ht2++) {
                    uint32_t vh[4];
                    ldsm_x4t(vh, smem_u32(&Vh[(kk2 * 16 + vx_row) * 72 + ht2 * 16 + vx_col]));
                    mma16816s(z[2 * ht2],     ahi, vh[0], vh[1]);
                    mma16816s(z[2 * ht2],     alo, vh[0], vh[1]);
                    mma16816s(z[2 * ht2 + 1], ahi, vh[2], vh[3]);
                    mma16816s(z[2 * ht2 + 1], alo, vh[2], vh[3]);
                }
            }
        }
    }

    // ---- finalize: z/l -> g_zh_hi ----
    float il0 = 1.0f / l0, il1 = 1.0f / l1;
#pragma unroll
    for (int ht = 0; ht < 8; ht++) {
        int col = ht * 8 + 2 * (lane & 3);
        size_t gi0 = (((size_t)b * SQ + qrow0) * NH + n) * H + col;
        __half2 h0 = __floats2half2_rn(z[ht][0] * il0, z[ht][1] * il0);
        *reinterpret_cast<uint32_t*>(&g_zh_hi[gi0]) = *reinterpret_cast<uint32_t*>(&h0);
        size_t gi1 = (((size_t)b * SQ + qrow1) * NH + n) * H + col;
        __half2 h1 = __floats2half2_rn(z[ht][2] * il1, z[ht][3] * il1);
        *reinterpret_cast<uint32_t*>(&g_zh_hi[gi1]) = *reinterpret_cast<uint32_t*>(&h1);
    }
}

// ---------------- launch ----------------
extern "C" void kernel_launch(void* const* d_in, const int* in_sizes, int n_in,
                              void* d_out, int out_size) {
    const float* x_q   = (const float*)d_in[0];
    const float* x_kv  = (const float*)d_in[1];
    const float* W_Q   = (const float*)d_in[3];
    const float* W_K   = (const float*)d_in[4];
    const float* W_V   = (const float*)d_in[5];
    const float* W_O   = (const float*)d_in[6];
    const float* b_Q   = (const float*)d_in[7];
    const float* b_K   = (const float*)d_in[8];
    const float* b_V   = (const float*)d_in[9];
    const float* b_O   = (const float*)d_in[10];
    const float* ln1_g = (const float*)d_in[11];
    const float* ln1_b = (const float*)d_in[12];
    const float* ln2_g = (const float*)d_in[13];
    const float* ln2_b = (const float*)d_in[14];

    float* out_f = (float*)d_out;
    float* k_out = nullptr;
    float* v_out = nullptr;
    if (out_size >= 3 * M * D) {
        k_out = out_f + (size_t)M * D;
        v_out = out_f + (size_t)2 * M * D;
    }

    cudaFuncSetAttribute(k_qkv,    cudaFuncAttributeMaxDynamicSharedMemorySize, GEMM_SMEM);
    cudaFuncSetAttribute(k_gemm_o, cudaFuncAttributeMaxDynamicSharedMemorySize, GEMM_SMEM);
    cudaFuncSetAttribute(k_attn,   cudaFuncAttributeMaxDynamicSharedMemorySize, ATT_SMEM);

    const int TPB = 256;
    k_convert_x<<<(M * D + TPB - 1) / TPB, TPB>>>(x_q, x_kv);
    k_convert_w<<<(D * D + TPB - 1) / TPB, TPB>>>(W_Q, W_K, W_V, W_O);

    dim3 qkvgrid(D / BN, M / BM, 3);   // (8, 32, 3)
    k_qkv<<<qkvgrid, 256, GEMM_SMEM>>>(b_Q, b_K, b_V, v_out);

    k_ln<0><<<(M * NH) / 8, 256>>>(ln1_g, ln1_b, nullptr);
    k_ln<1><<<(M * NH) / 8, 256>>>(ln2_g, ln2_b, k_out);

    dim3 agrid(SQ / 128, NH, B);       // (16, 16, 2)
    k_attn<<<agrid, 256, ATT_SMEM>>>();

    dim3 ogrid(D / BN, M / BM);        // (8, 32)
    k_gemm_o<<<ogrid, 256, GEMM_SMEM>>>(b_O, out_f);
}

// round 17
// speedup vs baseline: 1.0890x; 1.0890x over previous
#include <cuda_runtime.h>
#include <cuda_fp16.h>
#include <mma.h>
#include <stdint.h>

using namespace nvcuda;

constexpr int B  = 2;
constexpr int SQ = 2048;
constexpr int SK = 2048;
constexpr int D  = 1024;
constexpr int NH = 16;
constexpr int H  = 64;
constexpr int M  = B * SQ;
constexpr float EPS = 1e-5f;

// ---------------- device scratch ----------------
__device__ __align__(16) __half g_xq_hi [M * D];
__device__ __align__(16) __half g_xq_lo [M * D];
__device__ __align__(16) __half g_xkv_hi[M * D];
__device__ __align__(16) __half g_xkv_lo[M * D];
__device__ __align__(16) __half g_Wq_hi [D * D];
__device__ __align__(16) __half g_Wq_lo [D * D];
__device__ __align__(16) __half g_Wk_hi [D * D];
__device__ __align__(16) __half g_Wk_lo [D * D];
__device__ __align__(16) __half g_Wv_hi [D * D];
__device__ __align__(16) __half g_Wv_lo [D * D];
__device__ __align__(16) __half g_Wo_hi [D * D];
__device__ __align__(16) __half g_Wo_lo [D * D];
__device__ __align__(16) float  g_qf [M * D];
__device__ __align__(16) float  g_kf [M * D];
__device__ __align__(16) __half g_qh_hi[M * D];
__device__ __align__(16) __half g_qh_lo[M * D];
__device__ __align__(16) __half g_kh_hi[M * D];
__device__ __align__(16) __half g_kh_lo[M * D];
__device__ __align__(16) __half g_vh_hi[M * D];
__device__ __align__(16) __half g_zh_hi[M * D];

__device__ __forceinline__ void split2(float x, __half& hi, __half& lo) {
    __half h = __float2half(x);
    hi = h;
    lo = __float2half(x - __half2float(h));
}

__device__ __forceinline__ void cp16(void* dst, const void* src) {
    uint32_t d = (uint32_t)__cvta_generic_to_shared(dst);
    asm volatile("cp.async.cg.shared.global [%0], [%1], 16;\n" :: "r"(d), "l"(src));
}
__device__ __forceinline__ void cp_commit() { asm volatile("cp.async.commit_group;\n"); }
template <int N>
__device__ __forceinline__ void cp_wait() { asm volatile("cp.async.wait_group %0;\n" :: "n"(N)); }

// ---- mma.sync / ldmatrix primitives ----
__device__ __forceinline__ uint32_t smem_u32(const void* p) {
    return (uint32_t)__cvta_generic_to_shared(p);
}
__device__ __forceinline__ void ldsm_x4(uint32_t (&r)[4], uint32_t a) {
    asm volatile("ldmatrix.sync.aligned.m8n8.x4.shared.b16 {%0,%1,%2,%3}, [%4];"
                 : "=r"(r[0]), "=r"(r[1]), "=r"(r[2]), "=r"(r[3]) : "r"(a));
}
__device__ __forceinline__ void ldsm_x4t(uint32_t (&r)[4], uint32_t a) {
    asm volatile("ldmatrix.sync.aligned.m8n8.x4.trans.shared.b16 {%0,%1,%2,%3}, [%4];"
                 : "=r"(r[0]), "=r"(r[1]), "=r"(r[2]), "=r"(r[3]) : "r"(a));
}
__device__ __forceinline__ void mma16816s(float (&d)[4], const uint32_t (&a)[4],
                                          uint32_t b0, uint32_t b1) {
    asm volatile("mma.sync.aligned.m16n8k16.row.col.f32.f16.f16.f32 "
                 "{%0,%1,%2,%3}, {%4,%5,%6,%7}, {%8,%9}, {%0,%1,%2,%3};"
                 : "+f"(d[0]), "+f"(d[1]), "+f"(d[2]), "+f"(d[3])
                 : "r"(a[0]), "r"(a[1]), "r"(a[2]), "r"(a[3]), "r"(b0), "r"(b1));
}
__device__ __forceinline__ void split_pack(float f0, float f1, uint32_t& hi, uint32_t& lo) {
    __half h0 = __float2half_rn(f0), h1 = __float2half_rn(f1);
    __half2 hh = __halves2half2(h0, h1);
    hi = *reinterpret_cast<uint32_t*>(&hh);
    __half2 ll = __halves2half2(__float2half_rn(f0 - __half2float(h0)),
                                __float2half_rn(f1 - __half2float(h1)));
    lo = *reinterpret_cast<uint32_t*>(&ll);
}

// ---------------- merged conversion kernel ----------------
__global__ void k_convert(const float* __restrict__ xq, const float* __restrict__ xkv,
                          const float* __restrict__ WQ, const float* __restrict__ WK,
                          const float* __restrict__ WV, const float* __restrict__ WO) {
    int i = blockIdx.x * blockDim.x + threadIdx.x;
    if (i < M * D) {
        split2(xq [i], g_xq_hi [i], g_xq_lo [i]);
        split2(xkv[i], g_xkv_hi[i], g_xkv_lo[i]);
    }
    if (i < D * D) {
        int d   = i >> 10;
        int col = i & 1023;
        int n   = col >> 6;
        int h   = col & 63;
        int src = n * D * H + d * H + h;   // W[n][d][h] -> [D, N*H]
        split2(WQ[src], g_Wq_hi[i], g_Wq_lo[i]);
        split2(WK[src], g_Wk_hi[i], g_Wk_lo[i]);
        split2(WV[src], g_Wv_hi[i], g_Wv_lo[i]);
        split2(WO[i],   g_Wo_hi[i], g_Wo_lo[i]);  // [N,H,D] flat == [N*H,D]
    }
}

// ---------------- GEMM tiling: 128x128x32, 2-stage ----------------
constexpr int BM = 128, BN = 128, BK = 32;
constexpr int A_LD = 40;
constexpr int B_LD = 136;
constexpr int A_BYTES = BM * A_LD * 2;
constexpr int B_BYTES = BK * B_LD * 2;
constexpr int STAGE_BYTES = 2 * A_BYTES + 2 * B_BYTES;  // 37888
constexpr int GEMM_SMEM = 2 * STAGE_BYTES;              // 75776; Cs aliases
constexpr int C_LD = 132;

// ALO: include the A_lo * B_hi correction term (3-term split) or not (2-term).
template <bool ALO>
__device__ __forceinline__ void gemm_core(const __half* A_hi, const __half* A_lo,
                                          const __half* B_hi, const __half* B_lo,
                                          char* smem, int row0, int col0, int tid,
                                          wmma::fragment<wmma::accumulator, 16, 16, 16, float> (&acc)[4][2]) {
    const int warp   = tid >> 5;
    const int warp_m = warp >> 2;
    const int warp_n = warp & 3;

    auto load_stage = [&](int s, int k0) {
        char* st = smem + s * STAGE_BYTES;
        __half* sAh = (__half*)st;
        __half* sAl = (__half*)(st + A_BYTES);
        __half* sBh = (__half*)(st + 2 * A_BYTES);
        __half* sBl = (__half*)(st + 2 * A_BYTES + B_BYTES);
#pragma unroll
        for (int t = 0; t < 2; t++) {
            int idx = tid + t * 256;
            int ar = idx >> 2, ac = (idx & 3) * 8;
            size_t ai = (size_t)(row0 + ar) * D + k0 + ac;
            cp16(&sAh[ar * A_LD + ac], &A_hi[ai]);
            if (ALO) cp16(&sAl[ar * A_LD + ac], &A_lo[ai]);
            int br = idx >> 4, bc = (idx & 15) * 8;
            size_t bi = (size_t)(k0 + br) * D + col0 + bc;
            cp16(&sBh[br * B_LD + bc], &B_hi[bi]);
            cp16(&sBl[br * B_LD + bc], &B_lo[bi]);
        }
        cp_commit();
    };

#pragma unroll
    for (int i = 0; i < 4; i++)
#pragma unroll
        for (int j = 0; j < 2; j++) wmma::fill_fragment(acc[i][j], 0.0f);

    constexpr int NIT = D / BK;
    load_stage(0, 0);

    for (int it = 0; it < NIT; it++) {
        if (it + 1 < NIT) {
            load_stage((it + 1) & 1, (it + 1) * BK);
            cp_wait<1>();
        } else {
            cp_wait<0>();
        }
        __syncthreads();

        char* st = smem + (it & 1) * STAGE_BYTES;
        __half* sAh = (__half*)st;
        __half* sAl = (__half*)(st + A_BYTES);
        __half* sBh = (__half*)(st + 2 * A_BYTES);
        __half* sBl = (__half*)(st + 2 * A_BYTES + B_BYTES);

#pragma unroll
        for (int kf = 0; kf < 2; kf++) {
            wmma::fragment<wmma::matrix_a, 16, 16, 16, __half, wmma::row_major> ahi[4], alo[4];
#pragma unroll
            for (int mi = 0; mi < 4; mi++) {
                int r = warp_m * 64 + mi * 16;
                wmma::load_matrix_sync(ahi[mi], &sAh[r * A_LD + kf * 16], A_LD);
                if (ALO) wmma::load_matrix_sync(alo[mi], &sAl[r * A_LD + kf * 16], A_LD);
            }
#pragma unroll
            for (int ni = 0; ni < 2; ni++) {
                int c = warp_n * 32 + ni * 16;
                wmma::fragment<wmma::matrix_b, 16, 16, 16, __half, wmma::row_major> bhi, blo;
                wmma::load_matrix_sync(bhi, &sBh[kf * 16 * B_LD + c], B_LD);
                wmma::load_matrix_sync(blo, &sBl[kf * 16 * B_LD + c], B_LD);
#pragma unroll
                for (int mi = 0; mi < 4; mi++) {
                    wmma::mma_sync(acc[mi][ni], ahi[mi], bhi, acc[mi][ni]);
                    if (ALO) wmma::mma_sync(acc[mi][ni], alo[mi], bhi, acc[mi][ni]);
                    wmma::mma_sync(acc[mi][ni], ahi[mi], blo, acc[mi][ni]);
                }
            }
        }
        __syncthreads();
    }

    float* Cs = (float*)smem;
#pragma unroll
    for (int mi = 0; mi < 4; mi++)
#pragma unroll
        for (int ni = 0; ni < 2; ni++)
            wmma::store_matrix_sync(&Cs[(warp_m * 64 + mi * 16) * C_LD + warp_n * 32 + ni * 16],
                                    acc[mi][ni], C_LD, wmma::mem_row_major);
    __syncthreads();
}

// ---------------- fused QKV GEMM (Q/K 3-term; V 2-term) ----------------
__global__ __launch_bounds__(256) void k_qkv(const float* __restrict__ b_Q,
                                             const float* __restrict__ b_K,
                                             const float* __restrict__ b_V,
                                             float* __restrict__ v_out) {
    extern __shared__ __align__(16) char smem[];
    const int tid  = threadIdx.x;
    const int z    = blockIdx.z;
    const int row0 = blockIdx.y * BM;
    const int col0 = blockIdx.x * BN;

    wmma::fragment<wmma::accumulator, 16, 16, 16, float> acc[4][2];
    if (z == 0)
        gemm_core<true>(g_xq_hi, g_xq_lo, g_Wq_hi, g_Wq_lo, smem, row0, col0, tid, acc);
    else if (z == 1)
        gemm_core<true>(g_xkv_hi, g_xkv_lo, g_Wk_hi, g_Wk_lo, smem, row0, col0, tid, acc);
    else
        gemm_core<false>(g_xkv_hi, g_xkv_hi, g_Wv_hi, g_Wv_lo, smem, row0, col0, tid, acc);

    const float* bias = (z == 0) ? b_Q : (z == 1) ? b_K : b_V;
    float* Cs = (float*)smem;
    for (int idx = tid; idx < BM * BN; idx += 256) {
        int r = idx >> 7, c = idx & 127;
        float val = Cs[r * C_LD + c] + bias[col0 + c];
        size_t gi = (size_t)(row0 + r) * D + col0 + c;
        if (z == 0)      g_qf[gi] = val;
        else if (z == 1) g_kf[gi] = val;
        else {
            g_vh_hi[gi] = __float2half(val);
            if (v_out) v_out[gi] = val;
        }
    }
}

// ---------------- merged per-head LayerNorm (q: y=0, k: y=1) ----------------
__global__ void k_ln2(const float* __restrict__ ln1_g, const float* __restrict__ ln1_b,
                      const float* __restrict__ ln2_g, const float* __restrict__ ln2_b,
                      float* __restrict__ k_out) {
    const int sel = blockIdx.y;
    const float* in     = (sel == 0) ? g_qf    : g_kf;
    __half*      out_hi = (sel == 0) ? g_qh_hi : g_kh_hi;
    __half*      out_lo = (sel == 0) ? g_qh_lo : g_kh_lo;
    const float* g      = (sel == 0) ? ln1_g : ln2_g;
    const float* bb     = (sel == 0) ? ln1_b : ln2_b;
    float* out_f        = (sel == 0) ? nullptr : k_out;

    int row  = blockIdx.x * 8 + (threadIdx.x >> 5);
    int lane = threadIdx.x & 31;
    const float* p = in + (size_t)row * H;
    float v0 = p[lane], v1 = p[lane + 32];
    float s = v0 + v1;
#pragma unroll
    for (int o = 16; o; o >>= 1) s += __shfl_xor_sync(0xffffffffu, s, o);
    float mean = s * (1.0f / 64.0f);
    float d0 = v0 - mean, d1 = v1 - mean;
    float q = d0 * d0 + d1 * d1;
#pragma unroll
    for (int o = 16; o; o >>= 1) q += __shfl_xor_sync(0xffffffffu, q, o);
    float rstd = rsqrtf(q * (1.0f / 64.0f) + EPS);
    float o0 = d0 * rstd * g[lane]      + bb[lane];
    float o1 = d1 * rstd * g[lane + 32] + bb[lane + 32];
    size_t base = (size_t)row * H;
    split2(o0, out_hi[base + lane],      out_lo[base + lane]);
    split2(o1, out_hi[base + lane + 32], out_lo[base + lane + 32]);
    if (out_f) {
        out_f[base + lane]      = o0;
        out_f[base + lane + 32] = o1;
    }
}

// ---------------- O GEMM (2-term: zh_hi * (Wo_hi + Wo_lo)) ----------------
__global__ __launch_bounds__(256) void k_gemm_o(const float* __restrict__ bias,
                                                float* __restrict__ Cext) {
    extern __shared__ __align__(16) char smem[];
    const int tid  = threadIdx.x;
    const int row0 = blockIdx.y * BM;
    const int col0 = blockIdx.x * BN;

    wmma::fragment<wmma::accumulator, 16, 16, 16, float> acc[4][2];
    gemm_core<false>(g_zh_hi, g_zh_hi, g_Wo_hi, g_Wo_lo, smem, row0, col0, tid, acc);

    float* Cs = (float*)smem;
    for (int idx = tid; idx < BM * BN; idx += 256) {
        int r = idx >> 7, c = idx & 127;
        Cext[(size_t)(row0 + r) * D + col0 + c] = Cs[r * C_LD + c] + bias[col0 + c];
    }
}

// ---------------- flash attention: register S/P/Z, reversed qt order ----------
constexpr int ATT_QHI = 0;                       // 18432
constexpr int ATT_QLO = 18432;                   // 18432
constexpr int ATT_KV0 = 36864;
constexpr int KV_STAGE_B = 27648;                // Khi, Klo, Vhi
constexpr int ATT_SMEM = ATT_KV0 + 2 * KV_STAGE_B;   // 92160 -> 2 CTAs/SM

__global__ __launch_bounds__(256, 2) void k_attn() {
    extern __shared__ __align__(16) char sm[];
    __half* Qhi = (__half*)(sm + ATT_QHI);
    __half* Qlo = (__half*)(sm + ATT_QLO);

    const int qt = (gridDim.x - 1) - blockIdx.x;   // heavy diagonal tiles first
    const int n = blockIdx.y, b = blockIdx.z;
    const int tid = threadIdx.x, warp = tid >> 5, lane = tid & 31;
    const int qbase = qt * 128;
    const int qr0 = qbase + warp * 16;

    auto load_kv = [&](int j, int s) {
        char* st = sm + ATT_KV0 + s * KV_STAGE_B;
        __half* Kh = (__half*)st;
        __half* Kl = (__half*)(st + 9216);
        __half* Vh = (__half*)(st + 18432);
        const int kbase = j * 64;
#pragma unroll
        for (int t = 0; t < 2; t++) {
            int idx = tid + t * 256;
            int r = idx >> 3, c8 = (idx & 7) * 8;
            size_t gi = (((size_t)b * SK + kbase + r) * NH + n) * H + c8;
            cp16(&Kh[r * 72 + c8], &g_kh_hi[gi]);
            cp16(&Kl[r * 72 + c8], &g_kh_lo[gi]);
            cp16(&Vh[r * 72 + c8], &g_vh_hi[gi]);
        }
        cp_commit();
    };

    // Q tile load
#pragma unroll
    for (int t = 0; t < 4; t++) {
        int idx = tid + t * 256;
        int r = idx >> 3, c8 = (idx & 7) * 8;
        size_t gi = (((size_t)b * SQ + qbase + r) * NH + n) * H + c8;
        *(uint4*)&Qhi[r * 72 + c8] = *(const uint4*)&g_qh_hi[gi];
        *(uint4*)&Qlo[r * 72 + c8] = *(const uint4*)&g_qh_lo[gi];
    }
    load_kv(0, 0);

    float z[8][4];
#pragma unroll
    for (int ht = 0; ht < 8; ht++)
#pragma unroll
        for (int e = 0; e < 4; e++) z[ht][e] = 0.0f;
    float m0 = -1e30f, m1 = -1e30f, l0 = 0.0f, l1 = 0.0f;

    const int qrow0 = qr0 + (lane >> 2);
    const int qrow1 = qrow0 + 8;

    const int a_row  = lane & 15;
    const int a_col  = (lane >> 4) * 8;
    const int kx_row = ((lane & 16) >> 1) + (lane & 7);
    const int kx_col = (lane & 8);
    const int vx_row = (lane & 8) + (lane & 7);
    const int vx_col = ((lane & 16) >> 1);

    const int jmax = 2 * qt + 1;
    __syncthreads();

    for (int j = 0; j <= jmax; j++) {
        const int kbase = j * 64;
        const int s = j & 1;
        __syncthreads();                       // compute(j-1) done; buffer s^1 free
        if (j < jmax) { load_kv(j + 1, s ^ 1); cp_wait<1>(); }
        else          { cp_wait<0>(); }
        __syncthreads();                       // stage s visible

        const bool active = (kbase <= qr0 + 15);
        if (active) {
            char* st = sm + ATT_KV0 + s * KV_STAGE_B;
            __half* Kh = (__half*)st;
            __half* Kl = (__half*)(st + 9216);
            __half* Vh = (__half*)(st + 18432);
            const bool needmask = (kbase + 63 > qr0);

            // ---- S = Q @ K^T (3-term split) ----
            float sreg[8][4];
#pragma unroll
            for (int nt = 0; nt < 8; nt++)
#pragma unroll
                for (int e = 0; e < 4; e++) sreg[nt][e] = 0.0f;

#pragma unroll
            for (int kk = 0; kk < 4; kk++) {
                uint32_t qh[4], ql[4];
                ldsm_x4(qh, smem_u32(&Qhi[(warp * 16 + a_row) * 72 + kk * 16 + a_col]));
                ldsm_x4(ql, smem_u32(&Qlo[(warp * 16 + a_row) * 72 + kk * 16 + a_col]));
#pragma unroll
                for (int nt2 = 0; nt2 < 4; nt2++) {
                    uint32_t kh[4], kl[4];
                    ldsm_x4(kh, smem_u32(&Kh[(nt2 * 16 + kx_row) * 72 + kk * 16 + kx_col]));
                    ldsm_x4(kl, smem_u32(&Kl[(nt2 * 16 + kx_row) * 72 + kk * 16 + kx_col]));
                    mma16816s(sreg[2 * nt2],     qh, kh[0], kh[1]);
                    mma16816s(sreg[2 * nt2],     ql, kh[0], kh[1]);
                    mma16816s(sreg[2 * nt2],     qh, kl[0], kl[1]);
                    mma16816s(sreg[2 * nt2 + 1], qh, kh[2], kh[3]);
                    mma16816s(sreg[2 * nt2 + 1], ql, kh[2], kh[3]);
                    mma16816s(sreg[2 * nt2 + 1], qh, kl[2], kl[3]);
                }
            }

            // ---- online softmax in registers (guard-free exp) ----
            float mx0 = -1e30f, mx1 = -1e30f;
#pragma unroll
            for (int nt = 0; nt < 8; nt++) {
                int colg = kbase + nt * 8 + 2 * (lane & 3);
                if (needmask) {
                    if (colg     > qrow0) sreg[nt][0] = -1e30f;
                    if (colg + 1 > qrow0) sreg[nt][1] = -1e30f;
                    if (colg     > qrow1) sreg[nt][2] = -1e30f;
                    if (colg + 1 > qrow1) sreg[nt][3] = -1e30f;
                }
                mx0 = fmaxf(mx0, fmaxf(sreg[nt][0], sreg[nt][1]));
                mx1 = fmaxf(mx1, fmaxf(sreg[nt][2], sreg[nt][3]));
            }
            mx0 = fmaxf(mx0, __shfl_xor_sync(0xffffffffu, mx0, 1));
            mx0 = fmaxf(mx0, __shfl_xor_sync(0xffffffffu, mx0, 2));
            mx1 = fmaxf(mx1, __shfl_xor_sync(0xffffffffu, mx1, 1));
            mx1 = fmaxf(mx1, __shfl_xor_sync(0xffffffffu, mx1, 2));

            // mn is always finite in active iterations (j=0 row always has col 0
            // unmasked), so exp(-1e30 - mn) underflows cleanly to 0 — no guards.
            float mn0 = fmaxf(m0, mx0), mn1 = fmaxf(m1, mx1);
            float al0 = __expf(m0 - mn0), al1 = __expf(m1 - mn1);
            float sum0 = 0.0f, sum1 = 0.0f;
#pragma unroll
            for (int nt = 0; nt < 8; nt++) {
                float p0 = __expf(sreg[nt][0] - mn0);
                float p1 = __expf(sreg[nt][1] - mn0);
                float p2 = __expf(sreg[nt][2] - mn1);
                float p3 = __expf(sreg[nt][3] - mn1);
                sreg[nt][0] = p0; sreg[nt][1] = p1; sreg[nt][2] = p2; sreg[nt][3] = p3;
                sum0 += p0 + p1;
                sum1 += p2 + p3;
            }
            sum0 += __shfl_xor_sync(0xffffffffu, sum0, 1);
            sum0 += __shfl_xor_sync(0xffffffffu, sum0, 2);
            sum1 += __shfl_xor_sync(0xffffffffu, sum1, 1);
            sum1 += __shfl_xor_sync(0xffffffffu, sum1, 2);
            m0 = mn0; m1 = mn1;
            l0 = l0 * al0 + sum0;
            l1 = l1 * al1 + sum1;
#pragma unroll
            for (int ht = 0; ht < 8; ht++) {
                z[ht][0] *= al0; z[ht][1] *= al0;
                z[ht][2] *= al1; z[ht][3] *= al1;
            }

            // ---- Z += P @ V (P hi+lo, V hi only) ----
#pragma unroll
            for (int kk2 = 0; kk2 < 4; kk2++) {
                uint32_t ahi[4], alo[4];
                split_pack(sreg[2 * kk2][0],     sreg[2 * kk2][1],     ahi[0], alo[0]);
                split_pack(sreg[2 * kk2][2],     sreg[2 * kk2][3],     ahi[1], alo[1]);
                split_pack(sreg[2 * kk2 + 1][0], sreg[2 * kk2 + 1][1], ahi[2], alo[2]);
                split_pack(sreg[2 * kk2 + 1][2], sreg[2 * kk2 + 1][3], ahi[3], alo[3]);
#pragma unroll
                for (int ht2 = 0; ht2 < 4; ht2++) {
                    uint32_t vh[4];
                    ldsm_x4t(vh, smem_u32(&Vh[(kk2 * 16 + vx_row) * 72 + ht2 * 16 + vx_col]));
                    mma16816s(z[2 * ht2],     ahi, vh[0], vh[1]);
                    mma16816s(z[2 * ht2],     alo, vh[0], vh[1]);
                    mma16816s(z[2 * ht2 + 1], ahi, vh[2], vh[3]);
                    mma16816s(z[2 * ht2 + 1], alo, vh[2], vh[3]);
                }
            }
        }
    }

    // ---- finalize: z/l -> g_zh_hi ----
    float il0 = 1.0f / l0, il1 = 1.0f / l1;
#pragma unroll
    for (int ht = 0; ht < 8; ht++) {
        int col = ht * 8 + 2 * (lane & 3);
        size_t gi0 = (((size_t)b * SQ + qrow0) * NH + n) * H + col;
        __half2 h0 = __floats2half2_rn(z[ht][0] * il0, z[ht][1] * il0);
        *reinterpret_cast<uint32_t*>(&g_zh_hi[gi0]) = *reinterpret_cast<uint32_t*>(&h0);
        size_t gi1 = (((size_t)b * SQ + qrow1) * NH + n) * H + col;
        __half2 h1 = __floats2half2_rn(z[ht][2] * il1, z[ht][3] * il1);
        *reinterpret_cast<uint32_t*>(&g_zh_hi[gi1]) = *reinterpret_cast<uint32_t*>(&h1);
    }
}

// ---------------- launch ----------------
extern "C" void kernel_launch(void* const* d_in, const int* in_sizes, int n_in,
                              void* d_out, int out_size) {
    const float* x_q   = (const float*)d_in[0];
    const float* x_kv  = (const float*)d_in[1];
    const float* W_Q   = (const float*)d_in[3];
    const float* W_K   = (const float*)d_in[4];
    const float* W_V   = (const float*)d_in[5];
    const float* W_O   = (const float*)d_in[6];
    const float* b_Q   = (const float*)d_in[7];
    const float* b_K   = (const float*)d_in[8];
    const float* b_V   = (const float*)d_in[9];
    const float* b_O   = (const float*)d_in[10];
    const float* ln1_g = (const float*)d_in[11];
    const float* ln1_b = (const float*)d_in[12];
    const float* ln2_g = (const float*)d_in[13];
    const float* ln2_b = (const float*)d_in[14];

    float* out_f = (float*)d_out;
    float* k_out = nullptr;
    float* v_out = nullptr;
    if (out_size >= 3 * M * D) {
        k_out = out_f + (size_t)M * D;
        v_out = out_f + (size_t)2 * M * D;
    }

    cudaFuncSetAttribute(k_qkv,    cudaFuncAttributeMaxDynamicSharedMemorySize, GEMM_SMEM);
    cudaFuncSetAttribute(k_gemm_o, cudaFuncAttributeMaxDynamicSharedMemorySize, GEMM_SMEM);
    cudaFuncSetAttribute(k_attn,   cudaFuncAttributeMaxDynamicSharedMemorySize, ATT_SMEM);

    const int TPB = 256;
    k_convert<<<(M * D + TPB - 1) / TPB, TPB>>>(x_q, x_kv, W_Q, W_K, W_V, W_O);

    dim3 qkvgrid(D / BN, M / BM, 3);   // (8, 32, 3)
    k_qkv<<<qkvgrid, 256, GEMM_SMEM>>>(b_Q, b_K, b_V, v_out);

    dim3 lngrid((M * NH) / 8, 2);
    k_ln2<<<lngrid, 256>>>(ln1_g, ln1_b, ln2_g, ln2_b, k_out);

    dim3 agrid(SQ / 128, NH, B);       // (16, 16, 2)
    k_attn<<<agrid, 256, ATT_SMEM>>>();

    dim3 ogrid(D / BN, M / BM);        // (8, 32)
    k_gemm_o<<<ogrid, 256, GEMM_SMEM>>>(b_O, out_f);
}